// round 8
// baseline (speedup 1.0000x reference)
#include <cuda_runtime.h>
#include <cstdint>

#define N_BOX     8192
#define MAX_KEEP  256
#define MIN_SCORE 0.3f
#define NMS_THR   0.3f
#define NT        1024
#define NBKT      4096
#define NW        128          // 64-bit words per mask row (8192/64)
#define CH        256          // sweep chunk width (candidates)
#define CW        4            // words per chunk (256/64)
#define FULL      0xFFFFFFFFu

// ---------------- global scratch (static __device__, no allocation) ----------------
__device__ unsigned long long g_key[N_BOX];        // sorted keys (~score_bits, idx)
__device__ float4             g_cbox[N_BOX];       // sorted xyxy boxes
__device__ unsigned long long g_mask[N_BOX * NW];  // 8 MB suppression bitmask
__device__ int                g_nval;

// ================= kernel A: bucket sort (exact stable descending) =================
extern __shared__ unsigned char dynsmem[];

__global__ void __launch_bounds__(NT, 1)
sort_kernel(const float* __restrict__ score, const float* __restrict__ box)
{
    unsigned long long* s_key = (unsigned long long*)dynsmem;          // 64 KB
    unsigned int*       s_cnt = (unsigned int*)(dynsmem + 65536);      // 16 KB
    unsigned int*       s_off = (unsigned int*)(dynsmem + 81920);      // 16 KB
    __shared__ unsigned int s_wsum[32];
    __shared__ int s_nvalid;

    const int tid  = threadIdx.x;
    const int lane = tid & 31;
    const int wid  = tid >> 5;

    for (int i = tid; i < NBKT; i += NT) s_cnt[i] = 0;
    __syncthreads();

    float sc[8]; int bk[8];
    #pragma unroll
    for (int k = 0; k < 8; k++) {
        int i = tid + k * NT;
        float s = score[i];
        sc[k] = s;
        int b = -1;
        if (s >= MIN_SCORE) {
            b = 4095 - min(4095, (int)(s * 4096.0f));   // score desc -> bucket asc (monotone)
            atomicAdd(&s_cnt[b], 1u);
        }
        bk[k] = b;
    }
    __syncthreads();

    unsigned int c0 = s_cnt[tid*4+0], c1 = s_cnt[tid*4+1], c2 = s_cnt[tid*4+2], c3 = s_cnt[tid*4+3];
    unsigned int tsum = c0 + c1 + c2 + c3;
    unsigned int p = tsum;
    #pragma unroll
    for (int d = 1; d < 32; d <<= 1) {
        unsigned int v = __shfl_up_sync(FULL, p, d);
        if (lane >= d) p += v;
    }
    if (lane == 31) s_wsum[wid] = p;
    __syncthreads();
    if (wid == 0) {
        unsigned int w = s_wsum[lane];
        unsigned int q = w;
        #pragma unroll
        for (int d = 1; d < 32; d <<= 1) {
            unsigned int v = __shfl_up_sync(FULL, q, d);
            if (lane >= d) q += v;
        }
        s_wsum[lane] = q - w;
        if (lane == 31) s_nvalid = (int)q;
    }
    __syncthreads();
    unsigned int basep = s_wsum[wid] + (p - tsum);
    s_off[tid*4+0] = basep;
    s_off[tid*4+1] = basep + c0;
    s_off[tid*4+2] = basep + c0 + c1;
    s_off[tid*4+3] = basep + c0 + c1 + c2;
    __syncthreads();

    #pragma unroll
    for (int k = 0; k < 8; k++) {
        if (bk[k] >= 0) {
            int i = tid + k * NT;
            unsigned int pos = atomicAdd(&s_off[bk[k]], 1u);
            s_key[pos] = ((unsigned long long)(~__float_as_uint(sc[k])) << 32) | (unsigned int)i;
        }
    }
    __syncthreads();

    // intra-bucket insertion sort on full u64 key (exact total order)
    for (int b = tid; b < NBKT; b += NT) {
        int lo = b ? (int)s_off[b-1] : 0;
        int hi = (int)s_off[b];
        for (int i = lo + 1; i < hi; i++) {
            unsigned long long v = s_key[i];
            int j = i - 1;
            while (j >= lo && s_key[j] > v) { s_key[j+1] = s_key[j]; j--; }
            s_key[j+1] = v;
        }
    }
    __syncthreads();

    const int nval = s_nvalid;
    for (int c = tid; c < nval; c += NT) {
        unsigned long long key = s_key[c];
        g_key[c] = key;
        int idx = (int)(key & 0xFFFFFFFFull);
        float4 b4 = *(const float4*)(box + idx * 16);
        float hw = b4.z * 0.5f, hh = b4.w * 0.5f;
        g_cbox[c] = make_float4(b4.x - hw, b4.y - hh, b4.x + hw, b4.y + hh);
    }
    if (tid == 0) g_nval = nval;
}

// ================= kernel B: suppression bitmask matrix (multi-SM) =================
// block: 256 threads = 256 rows; grid (32, 128): (row tile, col word)
__global__ void __launch_bounds__(256)
mask_kernel()
{
    const int tj = blockIdx.y;               // col word 0..127
    const int i0 = blockIdx.x * 256;         // row tile base
    const int nval = g_nval;
    if (i0 >= nval) return;
    if (tj * 64 + 63 <= i0) return;          // whole tile has j <= all rows -> unread

    __shared__ float4 cb[64];
    __shared__ float  car[64];
    const int t = threadIdx.x;
    if (t < 64) {
        int j = tj * 64 + t;
        float4 b = (j < nval) ? g_cbox[j] : make_float4(0,0,0,0);
        cb[t]  = b;
        car[t] = (b.z - b.x) * (b.w - b.y);
    }
    __syncthreads();

    const int i = i0 + t;
    if (i >= nval) return;
    float4 B  = g_cbox[i];
    float  AR = (B.z - B.x) * (B.w - B.y);

    const int qlo  = max(0, i + 1 - tj * 64);             // strict j > i
    const int qmax = min(64, nval - tj * 64);
    unsigned long long w = 0;
    for (int q = qlo; q < qmax; q++) {
        float4 b = cb[q];
        float lx = fmaxf(B.x, b.x), ly = fmaxf(B.y, b.y);
        float rx = fminf(B.z, b.z), ry = fminf(B.w, b.w);
        float inter = fmaxf(rx - lx, 0.0f) * fmaxf(ry - ly, 0.0f);
        if (inter / (AR + car[q] - inter + 1e-9f) > NMS_THR)
            w |= 1ull << q;
    }
    g_mask[i * NW + tj] = w;
}

// ================= kernel C: serial sweep, 256-wide chunks (single block, 256 thr) =================
__device__ __forceinline__ unsigned long long valid_word(int nval, int w) {
    int bits = nval - w * 64;
    if (bits >= 64) return ~0ull;
    if (bits <= 0)  return 0ull;
    return (1ull << bits) - 1ull;
}

__global__ void __launch_bounds__(256, 1)
sweep_kernel(const float* __restrict__ box, float* __restrict__ out)
{
    __shared__ unsigned long long rem[NW];
    __shared__ unsigned long long diag[2][CH * CW];   // double-buffered 8 KB blocks
    __shared__ int klist[CH];
    __shared__ int keptidx[MAX_KEEP];
    __shared__ int s_kc, s_n;
    __shared__ int s_orig[MAX_KEEP];

    const int tid   = threadIdx.x;
    const int nval  = g_nval;
    const int nch   = (nval + CH - 1) / CH;
    const int nwords = (nval + 63) >> 6;

    if (tid < NW) rem[tid] = 0ull;
    if (tid == 0) { s_kc = 0; s_n = 0; }
    // preload diagonal block for chunk 0 (row tid, words 0..3)
    if (tid < nval) {
        #pragma unroll
        for (int d = 0; d < CW; d++)
            diag[0][tid * CW + d] = g_mask[tid * NW + d];
    }
    __syncthreads();

    for (int c = 0; c < nch; c++) {
        // prefetch next chunk's diagonal block (threads 128..255: 2 rows x 4 words each)
        if (tid >= 128 && c + 1 < nch) {
            int r0 = (tid - 128) * 2;
            #pragma unroll
            for (int rr = 0; rr < 2; rr++) {
                int r = r0 + rr;
                int i = (c + 1) * CH + r;
                if (i < nval) {
                    #pragma unroll
                    for (int d = 0; d < CW; d++)
                        diag[(c + 1) & 1][r * CW + d] = g_mask[i * NW + 4 * (c + 1) + d];
                }
            }
        }
        // thread 0: serial greedy resolve over this chunk
        if (tid == 0) {
            const unsigned long long* db = diag[c & 1];
            unsigned long long a0 = valid_word(nval, 4*c+0) & ~rem[4*c+0];
            unsigned long long a1 = valid_word(nval, 4*c+1) & ~rem[4*c+1];
            unsigned long long a2 = valid_word(nval, 4*c+2) & ~rem[4*c+2];
            unsigned long long a3 = valid_word(nval, 4*c+3) & ~rem[4*c+3];
            int kc = s_kc, n = 0;
            while (kc < MAX_KEEP) {
                int t;
                if      (a0) t = __ffsll((long long)a0) - 1;
                else if (a1) t = 64  + __ffsll((long long)a1) - 1;
                else if (a2) t = 128 + __ffsll((long long)a2) - 1;
                else if (a3) t = 192 + __ffsll((long long)a3) - 1;
                else break;
                keptidx[kc++] = c * CH + t;
                klist[n++] = t;
                a0 &= ~db[t * CW + 0];
                a1 &= ~db[t * CW + 1];
                a2 &= ~db[t * CW + 2];
                a3 &= ~db[t * CW + 3];
                // clear own bit (in case degenerate self-IoU didn't set it)
                if      (t < 64)  a0 &= ~(1ull << t);
                else if (t < 128) a1 &= ~(1ull << (t - 64));
                else if (t < 192) a2 &= ~(1ull << (t - 128));
                else              a3 &= ~(1ull << (t - 192));
            }
            s_kc = kc; s_n = n;
        }
        __syncthreads();

        // propagate new kept rows into rem for all future words
        const int n = s_n;
        if (n) {
            for (int w = 4 * (c + 1) + tid; w < nwords; w += 256) {
                unsigned long long acc = 0;
                for (int q = 0; q < n; q++)
                    acc |= g_mask[(c * CH + klist[q]) * NW + w];
                rem[w] |= acc;
            }
        }
        __syncthreads();
        if (s_kc >= MAX_KEEP) break;
    }

    // ---------------- outputs ----------------
    // layout: [0,256) score | [256,4352) box (256x16) | [4352,4608) valid
    const int kc = s_kc;
    for (int k = tid; k < MAX_KEEP; k += 256) {
        if (k < kc) {
            unsigned long long key = g_key[keptidx[k]];
            s_orig[k]     = (int)(key & 0xFFFFFFFFull);
            out[k]        = __uint_as_float(~(unsigned int)(key >> 32));
            out[4352 + k] = 1.0f;
        } else {
            out[k]        = 0.0f;
            out[4352 + k] = 0.0f;
        }
    }
    __syncthreads();
    for (int e = tid; e < MAX_KEEP * 16; e += 256) {
        int k = e >> 4, c = e & 15;
        out[256 + e] = (k < kc) ? box[s_orig[k] * 16 + c] : 0.0f;
    }
}

// ---------------- launch ----------------
extern "C" void kernel_launch(void* const* d_in, const int* in_sizes, int n_in,
                              void* d_out, int out_size) {
    const float* score = (const float*)d_in[0];
    const float* box   = (const float*)d_in[1];
    float* out = (float*)d_out;

    const int dynA = 98304;   // 64K keys + 16K hist + 16K offsets
    cudaFuncSetAttribute(sort_kernel,
                         cudaFuncAttributeMaxDynamicSharedMemorySize, dynA);

    sort_kernel<<<1, NT, dynA>>>(score, box);
    mask_kernel<<<dim3(32, 128), 256>>>();
    sweep_kernel<<<1, 256>>>(box, out);
}

// round 9
// speedup vs baseline: 1.3156x; 1.3156x over previous
#include <cuda_runtime.h>
#include <cstdint>

#define N_BOX     8192
#define MAX_KEEP  256
#define MIN_SCORE 0.3f
#define NMS_THR   0.3f
#define NT        1024
#define NBKT      4096
#define NCHUNK    128          // 8192 / 64
#define FULL      0xFFFFFFFFu

// ---------------- global scratch (static __device__, no allocation) ----------------
__device__ unsigned long long g_key[N_BOX];        // sorted keys (~score_bits, idx)
__device__ float4             g_cbox[N_BOX];       // sorted xyxy boxes
__device__ unsigned long long g_mask[N_BOX * NCHUNK];  // 8 MB suppression bitmask
__device__ int                g_nval;

// ================= kernel A: bucket sort (exact stable descending) =================
extern __shared__ unsigned char dynsmem[];

__global__ void __launch_bounds__(NT, 1)
sort_kernel(const float* __restrict__ score, const float* __restrict__ box)
{
    unsigned long long* s_key = (unsigned long long*)dynsmem;          // 64 KB
    unsigned int*       s_cnt = (unsigned int*)(dynsmem + 65536);      // 16 KB
    unsigned int*       s_off = (unsigned int*)(dynsmem + 81920);      // 16 KB
    __shared__ unsigned int s_wsum[32];
    __shared__ int s_nvalid;

    const int tid  = threadIdx.x;
    const int lane = tid & 31;
    const int wid  = tid >> 5;

    for (int i = tid; i < NBKT; i += NT) s_cnt[i] = 0;
    __syncthreads();

    float sc[8]; int bk[8];
    #pragma unroll
    for (int k = 0; k < 8; k++) {
        int i = tid + k * NT;
        float s = score[i];
        sc[k] = s;
        int b = -1;
        if (s >= MIN_SCORE) {
            b = 4095 - min(4095, (int)(s * 4096.0f));   // score desc -> bucket asc (monotone)
            atomicAdd(&s_cnt[b], 1u);
        }
        bk[k] = b;
    }
    __syncthreads();

    unsigned int c0 = s_cnt[tid*4+0], c1 = s_cnt[tid*4+1], c2 = s_cnt[tid*4+2], c3 = s_cnt[tid*4+3];
    unsigned int tsum = c0 + c1 + c2 + c3;
    unsigned int p = tsum;
    #pragma unroll
    for (int d = 1; d < 32; d <<= 1) {
        unsigned int v = __shfl_up_sync(FULL, p, d);
        if (lane >= d) p += v;
    }
    if (lane == 31) s_wsum[wid] = p;
    __syncthreads();
    if (wid == 0) {
        unsigned int w = s_wsum[lane];
        unsigned int q = w;
        #pragma unroll
        for (int d = 1; d < 32; d <<= 1) {
            unsigned int v = __shfl_up_sync(FULL, q, d);
            if (lane >= d) q += v;
        }
        s_wsum[lane] = q - w;
        if (lane == 31) s_nvalid = (int)q;
    }
    __syncthreads();
    unsigned int basep = s_wsum[wid] + (p - tsum);
    s_off[tid*4+0] = basep;
    s_off[tid*4+1] = basep + c0;
    s_off[tid*4+2] = basep + c0 + c1;
    s_off[tid*4+3] = basep + c0 + c1 + c2;
    __syncthreads();

    #pragma unroll
    for (int k = 0; k < 8; k++) {
        if (bk[k] >= 0) {
            int i = tid + k * NT;
            unsigned int pos = atomicAdd(&s_off[bk[k]], 1u);
            s_key[pos] = ((unsigned long long)(~__float_as_uint(sc[k])) << 32) | (unsigned int)i;
        }
    }
    __syncthreads();

    // intra-bucket insertion sort on full u64 key (exact total order)
    for (int b = tid; b < NBKT; b += NT) {
        int lo = b ? (int)s_off[b-1] : 0;
        int hi = (int)s_off[b];
        for (int i = lo + 1; i < hi; i++) {
            unsigned long long v = s_key[i];
            int j = i - 1;
            while (j >= lo && s_key[j] > v) { s_key[j+1] = s_key[j]; j--; }
            s_key[j+1] = v;
        }
    }
    __syncthreads();

    const int nval = s_nvalid;
    for (int c = tid; c < nval; c += NT) {
        unsigned long long key = s_key[c];
        g_key[c] = key;
        int idx = (int)(key & 0xFFFFFFFFull);
        float4 b4 = *(const float4*)(box + idx * 16);
        float hw = b4.z * 0.5f, hh = b4.w * 0.5f;
        g_cbox[c] = make_float4(b4.x - hw, b4.y - hh, b4.x + hw, b4.y + hh);
    }
    if (tid == 0) g_nval = nval;
}

// ================= kernel B: suppression bitmask matrix (multi-SM) =================
// block: 256 threads = 256 rows; grid (32, 128): (row tile, col word)
// Division-free IoU threshold test, bit-exact vs reference:
//   iou > THR  <=>  div(inter,denom) > THR.  A guarded multiply-compare decides
//   everything outside a +-1e-6 relative window around the threshold; inside the
//   window (expected ~tens of pairs out of 16M) fall back to the exact division.
__global__ void __launch_bounds__(256)
mask_kernel()
{
    const int tj = blockIdx.y;               // col word 0..127
    const int i0 = blockIdx.x * 256;         // row tile base
    const int nval = g_nval;
    if (i0 >= nval) return;
    if (tj * 64 + 63 <= i0) return;          // whole tile has j <= all rows -> unread

    __shared__ float4 cb[64];
    __shared__ float  car[64];
    const int t = threadIdx.x;
    if (t < 64) {
        int j = tj * 64 + t;
        float4 b = (j < nval) ? g_cbox[j] : make_float4(0,0,0,0);
        cb[t]  = b;
        car[t] = (b.z - b.x) * (b.w - b.y);
    }
    __syncthreads();

    const int i = i0 + t;
    if (i >= nval) return;
    float4 B  = g_cbox[i];
    float  AR = (B.z - B.x) * (B.w - B.y);

    const int qlo  = max(0, i + 1 - tj * 64);             // strict j > i
    const int qmax = min(64, nval - tj * 64);
    unsigned long long w = 0;
    #pragma unroll 4
    for (int q = qlo; q < qmax; q++) {
        float4 b = cb[q];
        float lx = fmaxf(B.x, b.x), ly = fmaxf(B.y, b.y);
        float rx = fminf(B.z, b.z), ry = fminf(B.w, b.w);
        float inter = fmaxf(rx - lx, 0.0f) * fmaxf(ry - ly, 0.0f);
        float denom = ((AR + car[q]) - inter) + 1e-9f;    // reference association order
        float thr   = denom * NMS_THR;
        bool hit;
        if (inter > thr * 1.000001f)      hit = true;     // definitely above threshold
        else if (inter < thr * 0.999999f) hit = false;    // definitely below
        else                              hit = (inter / denom) > NMS_THR;  // exact (rare)
        if (hit) w |= 1ull << q;
    }
    g_mask[i * NCHUNK + tj] = w;
}

// ================= kernel C: serial sweep + output (single block, 256 thr) =================
__global__ void __launch_bounds__(256, 1)
sweep_kernel(const float* __restrict__ box, float* __restrict__ out)
{
    __shared__ unsigned long long rem[NCHUNK];
    __shared__ unsigned long long colbuf[2][64];
    __shared__ int   klist[64];
    __shared__ int   keptidx[MAX_KEEP];
    __shared__ int   s_kc, s_kcn;
    __shared__ int   s_orig[MAX_KEEP];

    const int tid  = threadIdx.x;
    const int nval = g_nval;
    const int nchunk = (nval + 63) >> 6;

    if (tid < NCHUNK) rem[tid] = 0ull;
    if (tid == 0) { s_kc = 0; s_kcn = 0; }
    // preload column for chunk 0
    if (tid < 64 && tid < nval)
        colbuf[0][tid] = g_mask[tid * NCHUNK + 0];
    __syncthreads();

    for (int c = 0; c < nchunk; c++) {
        // prefetch next chunk's diagonal column (threads 192..255) while thread 0 resolves
        if (tid >= 192 && c + 1 < nchunk) {
            int t = tid - 192;
            int i = (c + 1) * 64 + t;
            if (i < nval)
                colbuf[(c + 1) & 1][t] = g_mask[i * NCHUNK + (c + 1)];
        }
        if (tid == 0) {
            int rembits = nval - c * 64;
            unsigned long long validw = (rembits >= 64) ? ~0ull : ((1ull << rembits) - 1ull);
            unsigned long long alive = validw & ~rem[c];
            const unsigned long long* col = colbuf[c & 1];
            int kc = s_kc, n = 0;
            while (alive && kc < MAX_KEEP) {
                int t = __ffsll((long long)alive) - 1;
                keptidx[kc++] = c * 64 + t;
                klist[n++] = t;
                alive &= ~col[t];
                alive &= ~(1ull << t);
            }
            s_kc = kc; s_kcn = n;
        }
        __syncthreads();

        const int n = s_kcn;
        if (n) {
            int w = c + 1 + tid;
            if (w < nchunk) {
                const int base = c * 64;
                unsigned long long acc = 0;
                for (int q = 0; q < n; q++)
                    acc |= g_mask[(base + klist[q]) * NCHUNK + w];
                rem[w] |= acc;
            }
        }
        __syncthreads();
        if (s_kc >= MAX_KEEP) break;
    }

    // ---------------- outputs ----------------
    // layout: [0,256) score | [256,4352) box (256x16) | [4352,4608) valid
    const int kc = s_kc;
    for (int k = tid; k < MAX_KEEP; k += 256) {
        if (k < kc) {
            unsigned long long key = g_key[keptidx[k]];
            s_orig[k]     = (int)(key & 0xFFFFFFFFull);
            out[k]        = __uint_as_float(~(unsigned int)(key >> 32));
            out[4352 + k] = 1.0f;
        } else {
            out[k]        = 0.0f;
            out[4352 + k] = 0.0f;
        }
    }
    __syncthreads();
    for (int e = tid; e < MAX_KEEP * 16; e += 256) {
        int k = e >> 4, c = e & 15;
        out[256 + e] = (k < kc) ? box[s_orig[k] * 16 + c] : 0.0f;
    }
}

// ---------------- launch ----------------
extern "C" void kernel_launch(void* const* d_in, const int* in_sizes, int n_in,
                              void* d_out, int out_size) {
    const float* score = (const float*)d_in[0];
    const float* box   = (const float*)d_in[1];
    float* out = (float*)d_out;

    const int dynA = 98304;   // 64K keys + 16K hist + 16K offsets
    cudaFuncSetAttribute(sort_kernel,
                         cudaFuncAttributeMaxDynamicSharedMemorySize, dynA);

    sort_kernel<<<1, NT, dynA>>>(score, box);
    mask_kernel<<<dim3(32, 128), 256>>>();
    sweep_kernel<<<1, 256>>>(box, out);
}